// round 10
// baseline (speedup 1.0000x reference)
#include <cuda_runtime.h>
#include <cuda_fp16.h>
#include <cstdint>

// Problem constants
#define B_TOT 12288   // features(4096) + queue(8192)
#define N_OUT 4096
#define KCLS  1000
#define KPAD  1024
#define DDIM  256
#define INV_EPS 20.0f

// ---------------------------------------------------------------------------
// Device scratch (allocation-free)
// ---------------------------------------------------------------------------
__device__ float   g_E[B_TOT * KPAD];   // exp(logits/eps), [b, 1024] (50 MB)
__device__ __half  g_Ah[B_TOT * DDIM];  // normalized features, fp16
__device__ __half  g_Bh[KPAD * DDIM];   // normalized head^T, fp16 (pad rows stay 0)
__device__ float   g_u[KPAD];
__device__ float   g_r[KPAD];
__device__ double  g_S;
__device__ int     g_cnt;               // last-block ticket (self-resetting)

__device__ __forceinline__ float warp_sum(float v) {
    #pragma unroll
    for (int o = 16; o > 0; o >>= 1) v += __shfl_down_sync(0xFFFFFFFFu, v, o);
    return v;
}

__device__ __forceinline__ uint32_t smem_u32(const void* p) {
    uint32_t a;
    asm("{ .reg .u64 t; cvta.to.shared.u64 t, %1; cvt.u32.u64 %0, t; }" : "=r"(a) : "l"(p));
    return a;
}

#define SW64(o) ((o) ^ (((o) >> 3) & 0x30))

__device__ __forceinline__ void ldsm_x4(uint32_t& r0, uint32_t& r1, uint32_t& r2, uint32_t& r3,
                                        uint32_t addr) {
    asm volatile("ldmatrix.sync.aligned.m8n8.x4.shared.b16 {%0,%1,%2,%3}, [%4];"
                 : "=r"(r0), "=r"(r1), "=r"(r2), "=r"(r3) : "r"(addr));
}

__device__ __forceinline__ void mma_f16(float* d, const uint32_t* a, const uint32_t* b) {
    asm volatile(
        "mma.sync.aligned.m16n8k16.row.col.f32.f16.f16.f32 "
        "{%0,%1,%2,%3}, {%4,%5,%6,%7}, {%8,%9}, {%0,%1,%2,%3};"
        : "+f"(d[0]), "+f"(d[1]), "+f"(d[2]), "+f"(d[3])
        : "r"(a[0]), "r"(a[1]), "r"(a[2]), "r"(a[3]), "r"(b[0]), "r"(b[1]));
}

__device__ __forceinline__ void cp_async16(uint32_t dst, const void* src) {
    asm volatile("cp.async.cg.shared.global [%0], [%1], 16;" :: "r"(dst), "l"(src));
}
__device__ __forceinline__ void cp_commit() {
    asm volatile("cp.async.commit_group;" ::: "memory");
}
template <int N> __device__ __forceinline__ void cp_wait() {
    asm volatile("cp.async.wait_group %0;" :: "n"(N) : "memory");
}

// Shared helper: compute r from (S, u), zero u, reset ticket. Call from the
// LAST block of a kernel (all threads of that block).
__device__ __forceinline__ void finalize_r(int tid) {
    double S = g_S;
    for (int k = tid; k < KPAD; k += 256) {
        float u;
        asm volatile("ld.global.cg.f32 %0, [%1];" : "=f"(u) : "l"(&g_u[k]));
        g_r[k] = (k < KCLS) ? (float)(S / ((double)KCLS * (double)u)) : 0.f;
        g_u[k] = 0.f;
    }
    if (tid == 0) g_cnt = 0;
}

// ---------------------------------------------------------------------------
// 1. Normalize feature rows -> fp16. One warp per row. Block 0 zeroes g_S.
// ---------------------------------------------------------------------------
__global__ __launch_bounds__(256) void k_prep_feat(const float* __restrict__ features,
                                                   const float* __restrict__ queue) {
    if (blockIdx.x == 0 && threadIdx.x == 0) g_S = 0.0;
    int gwarp = (blockIdx.x * blockDim.x + threadIdx.x) >> 5;
    int lane  = threadIdx.x & 31;
    if (gwarp >= B_TOT) return;
    const float* row = (gwarp < N_OUT) ? (features + (size_t)gwarp * DDIM)
                                       : (queue + (size_t)(gwarp - N_OUT) * DDIM);
    float x[8];
    const float4* r4 = reinterpret_cast<const float4*>(row + lane * 8);
    float4 v0 = r4[0], v1 = r4[1];
    x[0]=v0.x; x[1]=v0.y; x[2]=v0.z; x[3]=v0.w;
    x[4]=v1.x; x[5]=v1.y; x[6]=v1.z; x[7]=v1.w;
    float ss = 0.f;
    #pragma unroll
    for (int i = 0; i < 8; i++) ss += x[i] * x[i];
    ss = warp_sum(ss);
    ss = __shfl_sync(0xFFFFFFFFu, ss, 0);
    float inv = 1.0f / fmaxf(sqrtf(ss), 1e-12f);
    __half h[8];
    #pragma unroll
    for (int i = 0; i < 8; i++) h[i] = __float2half(x[i] * inv);
    *reinterpret_cast<uint4*>(&g_Ah[(size_t)gwarp * DDIM + lane * 8]) =
        *reinterpret_cast<uint4*>(h);
}

// ---------------------------------------------------------------------------
// 2. Normalize head rows (dim=1), write TRANSPOSED fp16: Bh[n,d]=Hs[d,n]
// ---------------------------------------------------------------------------
__global__ __launch_bounds__(256) void k_prep_head(const float* __restrict__ head) {
    int d = blockIdx.x;
    const float* row = head + (size_t)d * KCLS;
    float ss = 0.f;
    for (int k = threadIdx.x; k < KCLS; k += 256) {
        float v = row[k];
        ss += v * v;
    }
    __shared__ float sred[8];
    ss = warp_sum(ss);
    if ((threadIdx.x & 31) == 0) sred[threadIdx.x >> 5] = ss;
    __syncthreads();
    if (threadIdx.x < 8) {
        float s = sred[threadIdx.x];
        #pragma unroll
        for (int o = 4; o > 0; o >>= 1) s += __shfl_down_sync(0xFFu, s, o);
        if (threadIdx.x == 0) sred[0] = 1.0f / fmaxf(sqrtf(s), 1e-12f);
    }
    __syncthreads();
    float inv = sred[0];
    for (int k = threadIdx.x; k < KCLS; k += 256)
        g_Bh[(size_t)k * DDIM + d] = __float2half(row[k] * inv);
}

// ---------------------------------------------------------------------------
// 3. HMMA GEMM + exp, single fp16 pass, 3-stage cp.async pipeline.
//    128x128 CTA tile; 8 warps (2m x 4n); K in 8 chunks of 32.
//    Last block computes r1 from (S, u0) and zeroes u.
// ---------------------------------------------------------------------------
#define CH 32
#define NCH 8
#define TILE_BYTES 8192                   // 128 rows x 64B
#define STAGE_BYTES (2 * TILE_BYTES)      // A, B
#define NSTAGE 3
#define SMEM_GEMM_TOTAL (NSTAGE * STAGE_BYTES + 512)
#define GEMM_GRID (8 * 96)

__device__ __forceinline__ void load_stage(uint32_t sbase, int buf, int b0, int n0,
                                           int c, int tid) {
    uint32_t dstb = sbase + (uint32_t)buf * STAGE_BYTES;
    #pragma unroll
    for (int j = 0; j < 2; j++) {
        int slot = tid + j * 256;          // 0..511
        int row  = slot >> 2;
        int c16  = slot & 3;
        uint32_t sw = SW64((uint32_t)(row * 64 + c16 * 16));
        size_t gA = (size_t)(b0 + row) * DDIM + c * CH + c16 * 8;
        size_t gB = (size_t)(n0 + row) * DDIM + c * CH + c16 * 8;
        cp_async16(dstb + 0 * TILE_BYTES + sw, &g_Ah[gA]);
        cp_async16(dstb + 1 * TILE_BYTES + sw, &g_Bh[gB]);
    }
}

__global__ __launch_bounds__(256, 2) void k_gemm_mma() {
    extern __shared__ char smem[];
    float* scol = reinterpret_cast<float*>(smem + NSTAGE * STAGE_BYTES);
    __shared__ int sLast;
    uint32_t sbase = smem_u32(smem);

    int tid = threadIdx.x, wid = tid >> 5, lane = tid & 31;
    int n0 = blockIdx.x * 128;
    int b0 = blockIdx.y * 128;
    int wm = (wid & 1) * 64;
    int wn = (wid >> 1) * 32;

    float acc[4][4][4];
    #pragma unroll
    for (int i = 0; i < 4; i++)
        #pragma unroll
        for (int j = 0; j < 4; j++)
            #pragma unroll
            for (int q = 0; q < 4; q++) acc[i][j][q] = 0.f;

    int a_row  = (lane & 7) + ((lane >> 3) & 1) * 8;
    int a_colb = (lane >> 4) * 16;
    int b_row  = (lane & 7) + ((lane >> 4) & 1) * 8;
    int b_colb = ((lane >> 3) & 1) * 16;

    #pragma unroll
    for (int s = 0; s < NSTAGE; s++) { load_stage(sbase, s, b0, n0, s, tid); cp_commit(); }

    for (int c = 0; c < NCH; c++) {
        cp_wait<NSTAGE - 1>();
        __syncthreads();
        uint32_t tb = sbase + (uint32_t)(c % NSTAGE) * STAGE_BYTES;

        #pragma unroll
        for (int ks = 0; ks < 2; ks++) {
            uint32_t a[4][4], bh[4][2];
            #pragma unroll
            for (int np = 0; np < 2; np++) {
                uint32_t sw = SW64((uint32_t)((wn + np * 16 + b_row) * 64 + ks * 32 + b_colb));
                ldsm_x4(bh[np*2][0], bh[np*2][1], bh[np*2+1][0], bh[np*2+1][1],
                        tb + 1 * TILE_BYTES + sw);
            }
            #pragma unroll
            for (int mt = 0; mt < 4; mt++) {
                uint32_t sw = SW64((uint32_t)((wm + mt * 16 + a_row) * 64 + ks * 32 + a_colb));
                ldsm_x4(a[mt][0], a[mt][1], a[mt][2], a[mt][3], tb + 0 * TILE_BYTES + sw);
            }
            #pragma unroll
            for (int mt = 0; mt < 4; mt++)
                #pragma unroll
                for (int nt = 0; nt < 4; nt++)
                    mma_f16(acc[mt][nt], a[mt], bh[nt]);
        }
        __syncthreads();
        if (c + NSTAGE < NCH) load_stage(sbase, c % NSTAGE, b0, n0, c + NSTAGE, tid);
        cp_commit();
    }

    // ---- Epilogue: exp, direct stores, column sums ----
    if (tid < 128) scol[tid] = 0.f;
    __syncthreads();

    int g = lane >> 2;
    int t2 = (lane & 3) * 2;
    float csum[4][2];
    #pragma unroll
    for (int nt = 0; nt < 4; nt++) { csum[nt][0] = 0.f; csum[nt][1] = 0.f; }

    #pragma unroll
    for (int mt = 0; mt < 4; mt++) {
        int r0 = b0 + wm + mt * 16 + g;
        #pragma unroll
        for (int nt = 0; nt < 4; nt++) {
            int col = n0 + wn + nt * 8 + t2;
            float2 e0, e1;
            e0.x = __expf(INV_EPS * acc[mt][nt][0]);
            e0.y = __expf(INV_EPS * acc[mt][nt][1]);
            e1.x = __expf(INV_EPS * acc[mt][nt][2]);
            e1.y = __expf(INV_EPS * acc[mt][nt][3]);
            *reinterpret_cast<float2*>(&g_E[(size_t)r0 * KPAD + col]) = e0;
            *reinterpret_cast<float2*>(&g_E[(size_t)(r0 + 8) * KPAD + col]) = e1;
            csum[nt][0] += e0.x + e1.x;
            csum[nt][1] += e0.y + e1.y;
        }
    }
    #pragma unroll
    for (int nt = 0; nt < 4; nt++) {
        atomicAdd(&scol[wn + nt * 8 + t2],     csum[nt][0]);
        atomicAdd(&scol[wn + nt * 8 + t2 + 1], csum[nt][1]);
    }
    __syncthreads();

    if (tid < 128) atomicAdd(&g_u[n0 + tid], scol[tid]);  // pads land in g_u[1000..1023]
    if (tid < 32) {
        float s = 0.f;
        #pragma unroll
        for (int i = 0; i < 4; i++) {
            int k = tid + i * 32;
            if (n0 + k < KCLS) s += scol[k];
        }
        s = warp_sum(s);
        if (tid == 0) atomicAdd(&g_S, (double)s);
    }

    // ---- Last block computes r1, zeroes u ----
    __threadfence();
    __syncthreads();
    if (tid == 0) sLast = (atomicAdd(&g_cnt, 1) == GEMM_GRID - 1);
    __syncthreads();
    if (sLast) finalize_r(tid);
}

// ---------------------------------------------------------------------------
// 4. Fused pass, BLOCK-PER-ROW with cross-row prefetch (pipelined stream):
//    thread t owns float4 column slot t (256*4 = 1024 = KPAD).
//    Per row: v = block_reduce(e.r); cb = S/(B v); uacc += e*cb (registers).
//    Grid-stride over rows; one spread atomic flush per thread at the end.
// ---------------------------------------------------------------------------
#define VCU_GRID 1184      // 8 blocks per SM
__global__ __launch_bounds__(256) void k_vcu() {
    __shared__ float sred[8];
    __shared__ float scb;
    __shared__ int sLast;
    int tid = threadIdx.x, warp = tid >> 5, lane = tid & 31;

    double Sd = g_S;
    const float4* E4 = reinterpret_cast<const float4*>(g_E);
    float4 r = __ldg(&reinterpret_cast<const float4*>(g_r)[tid]);
    float4 uacc = make_float4(0.f, 0.f, 0.f, 0.f);

    int b = blockIdx.x;
    float4 e = E4[(size_t)b * 256 + tid];
    while (true) {
        int bn = b + VCU_GRID;
        float4 en;
        if (bn < B_TOT) en = E4[(size_t)bn * 256 + tid];   // prefetch next row

        // block reduce v over current row (2 syncs; prefetch in flight)
        float v = e.x * r.x + e.y * r.y + e.z * r.z + e.w * r.w;
        v = warp_sum(v);
        if (lane == 0) sred[warp] = v;
        __syncthreads();
        if (tid == 0) {
            float vv = sred[0] + sred[1] + sred[2] + sred[3]
                     + sred[4] + sred[5] + sred[6] + sred[7];
            scb = (float)(Sd / ((double)B_TOT * (double)vv));
        }
        __syncthreads();
        float cb = scb;
        uacc.x += e.x * cb; uacc.y += e.y * cb;
        uacc.z += e.z * cb; uacc.w += e.w * cb;

        if (bn >= B_TOT) break;
        b = bn; e = en;
    }

    // Spread atomic flush (1184 x 1024 REDG over 1024 addresses)
    atomicAdd(&g_u[tid * 4 + 0], uacc.x);
    atomicAdd(&g_u[tid * 4 + 1], uacc.y);
    atomicAdd(&g_u[tid * 4 + 2], uacc.z);
    atomicAdd(&g_u[tid * 4 + 3], uacc.w);

    // ---- Last block computes next r, zeroes u ----
    __threadfence();
    __syncthreads();
    if (tid == 0) sLast = (atomicAdd(&g_cnt, 1) == VCU_GRID - 1);
    __syncthreads();
    if (sLast) finalize_r(tid);
}

// ---------------------------------------------------------------------------
// 5. Final fused pass (rows 0..4095), BLOCK-PER-ROW pipelined:
//    v_b = E[b,:].r3 ; out[b,:] = E[b,:] * r3 / v_b.
// ---------------------------------------------------------------------------
#define FIN_GRID 1024
__global__ __launch_bounds__(256) void k_final(float* __restrict__ out) {
    __shared__ float sred[8];
    __shared__ float sinv;
    int tid = threadIdx.x, warp = tid >> 5, lane = tid & 31;

    const float4* E4 = reinterpret_cast<const float4*>(g_E);
    float4 r = __ldg(&reinterpret_cast<const float4*>(g_r)[tid]);

    int b = blockIdx.x;
    float4 e = E4[(size_t)b * 256 + tid];
    while (true) {
        int bn = b + FIN_GRID;
        float4 en;
        if (bn < N_OUT) en = E4[(size_t)bn * 256 + tid];   // prefetch next row

        float v = e.x * r.x + e.y * r.y + e.z * r.z + e.w * r.w;
        v = warp_sum(v);
        if (lane == 0) sred[warp] = v;
        __syncthreads();
        if (tid == 0) {
            float vv = sred[0] + sred[1] + sred[2] + sred[3]
                     + sred[4] + sred[5] + sred[6] + sred[7];
            sinv = 1.0f / vv;
        }
        __syncthreads();
        float invv = sinv;
        if (tid < KCLS / 4) {                // 250 threads store; pads dropped
            float4 o;
            o.x = e.x * r.x * invv;
            o.y = e.y * r.y * invv;
            o.z = e.z * r.z * invv;
            o.w = e.w * r.w * invv;
            *reinterpret_cast<float4*>(out + (size_t)b * KCLS + tid * 4) = o;
        }

        if (bn >= N_OUT) break;
        b = bn; e = en;
    }
}

// ---------------------------------------------------------------------------
extern "C" void kernel_launch(void* const* d_in, const int* in_sizes, int n_in,
                              void* d_out, int out_size) {
    const float* features = (const float*)d_in[0];
    const float* head     = (const float*)d_in[1];
    const float* queue    = (const float*)d_in[2];
    float* out = (float*)d_out;

    cudaFuncSetAttribute(k_gemm_mma, cudaFuncAttributeMaxDynamicSharedMemorySize,
                         SMEM_GEMM_TOTAL);

    k_prep_feat<<<(B_TOT * 32) / 256, 256>>>(features, queue);
    k_prep_head<<<DDIM, 256>>>(head);
    k_gemm_mma<<<dim3(KPAD / 128, B_TOT / 128), 256, SMEM_GEMM_TOTAL>>>();  // + r1
    k_vcu<<<VCU_GRID, 256>>>();   // iter1 col-step + iter2 row-sum -> r2
    k_vcu<<<VCU_GRID, 256>>>();   // iter2 col-step + iter3 row-sum -> r3
    k_final<<<FIN_GRID, 256>>>(out);  // iter3 col-step fused with output
}

// round 12
// speedup vs baseline: 1.5061x; 1.5061x over previous
#include <cuda_runtime.h>
#include <cuda_fp16.h>
#include <cstdint>

// Problem constants
#define B_TOT 12288   // features(4096) + queue(8192)
#define N_OUT 4096
#define KCLS  1000
#define KPAD  1024
#define DDIM  256
#define INV_EPS 20.0f

// ---------------------------------------------------------------------------
// Device scratch (allocation-free)
// ---------------------------------------------------------------------------
__device__ float   g_E[B_TOT * KPAD];   // exp(logits/eps), [b, 1024] (50 MB)
__device__ __half  g_Ah[B_TOT * DDIM];  // normalized features, fp16
__device__ __half  g_Bh[KPAD * DDIM];   // normalized head^T, fp16 (pad rows stay 0)
__device__ float   g_u[KPAD];
__device__ float   g_r[KPAD];
__device__ double  g_S;
__device__ float   g_SfB;               // (float)(S / B_TOT), set by finalize_r
__device__ int     g_cnt;               // last-block ticket (self-resetting)

__device__ __forceinline__ float warp_sum(float v) {
    #pragma unroll
    for (int o = 16; o > 0; o >>= 1) v += __shfl_down_sync(0xFFFFFFFFu, v, o);
    return v;
}

__device__ __forceinline__ uint32_t smem_u32(const void* p) {
    uint32_t a;
    asm("{ .reg .u64 t; cvta.to.shared.u64 t, %1; cvt.u32.u64 %0, t; }" : "=r"(a) : "l"(p));
    return a;
}

#define SW64(o) ((o) ^ (((o) >> 3) & 0x30))

__device__ __forceinline__ void ldsm_x4(uint32_t& r0, uint32_t& r1, uint32_t& r2, uint32_t& r3,
                                        uint32_t addr) {
    asm volatile("ldmatrix.sync.aligned.m8n8.x4.shared.b16 {%0,%1,%2,%3}, [%4];"
                 : "=r"(r0), "=r"(r1), "=r"(r2), "=r"(r3) : "r"(addr));
}

__device__ __forceinline__ void mma_f16(float* d, const uint32_t* a, const uint32_t* b) {
    asm volatile(
        "mma.sync.aligned.m16n8k16.row.col.f32.f16.f16.f32 "
        "{%0,%1,%2,%3}, {%4,%5,%6,%7}, {%8,%9}, {%0,%1,%2,%3};"
        : "+f"(d[0]), "+f"(d[1]), "+f"(d[2]), "+f"(d[3])
        : "r"(a[0]), "r"(a[1]), "r"(a[2]), "r"(a[3]), "r"(b[0]), "r"(b[1]));
}

__device__ __forceinline__ void cp_async16(uint32_t dst, const void* src) {
    asm volatile("cp.async.cg.shared.global [%0], [%1], 16;" :: "r"(dst), "l"(src));
}
__device__ __forceinline__ void cp_commit() {
    asm volatile("cp.async.commit_group;" ::: "memory");
}
template <int N> __device__ __forceinline__ void cp_wait() {
    asm volatile("cp.async.wait_group %0;" :: "n"(N) : "memory");
}

// Shared helper: compute r from (S, u), zero u, reset ticket, publish S/B as
// float. Call from the LAST block of a kernel (all threads of that block).
__device__ __forceinline__ void finalize_r(int tid) {
    double S = g_S;
    for (int k = tid; k < KPAD; k += 256) {
        float u;
        asm volatile("ld.global.cg.f32 %0, [%1];" : "=f"(u) : "l"(&g_u[k]));
        g_r[k] = (k < KCLS) ? (float)(S / ((double)KCLS * (double)u)) : 0.f;
        g_u[k] = 0.f;
    }
    if (tid == 0) {
        g_SfB = (float)(S / (double)B_TOT);
        g_cnt = 0;
    }
}

// ---------------------------------------------------------------------------
// 1. Normalize feature rows -> fp16. One warp per row. Block 0 zeroes g_S.
// ---------------------------------------------------------------------------
__global__ __launch_bounds__(256) void k_prep_feat(const float* __restrict__ features,
                                                   const float* __restrict__ queue) {
    if (blockIdx.x == 0 && threadIdx.x == 0) g_S = 0.0;
    int gwarp = (blockIdx.x * blockDim.x + threadIdx.x) >> 5;
    int lane  = threadIdx.x & 31;
    if (gwarp >= B_TOT) return;
    const float* row = (gwarp < N_OUT) ? (features + (size_t)gwarp * DDIM)
                                       : (queue + (size_t)(gwarp - N_OUT) * DDIM);
    float x[8];
    const float4* r4 = reinterpret_cast<const float4*>(row + lane * 8);
    float4 v0 = r4[0], v1 = r4[1];
    x[0]=v0.x; x[1]=v0.y; x[2]=v0.z; x[3]=v0.w;
    x[4]=v1.x; x[5]=v1.y; x[6]=v1.z; x[7]=v1.w;
    float ss = 0.f;
    #pragma unroll
    for (int i = 0; i < 8; i++) ss += x[i] * x[i];
    ss = warp_sum(ss);
    ss = __shfl_sync(0xFFFFFFFFu, ss, 0);
    float inv = 1.0f / fmaxf(sqrtf(ss), 1e-12f);
    __half h[8];
    #pragma unroll
    for (int i = 0; i < 8; i++) h[i] = __float2half(x[i] * inv);
    *reinterpret_cast<uint4*>(&g_Ah[(size_t)gwarp * DDIM + lane * 8]) =
        *reinterpret_cast<uint4*>(h);
}

// ---------------------------------------------------------------------------
// 2. Normalize head rows (dim=1), write TRANSPOSED fp16: Bh[n,d]=Hs[d,n]
// ---------------------------------------------------------------------------
__global__ __launch_bounds__(256) void k_prep_head(const float* __restrict__ head) {
    int d = blockIdx.x;
    const float* row = head + (size_t)d * KCLS;
    float ss = 0.f;
    for (int k = threadIdx.x; k < KCLS; k += 256) {
        float v = row[k];
        ss += v * v;
    }
    __shared__ float sred[8];
    ss = warp_sum(ss);
    if ((threadIdx.x & 31) == 0) sred[threadIdx.x >> 5] = ss;
    __syncthreads();
    if (threadIdx.x < 8) {
        float s = sred[threadIdx.x];
        #pragma unroll
        for (int o = 4; o > 0; o >>= 1) s += __shfl_down_sync(0xFFu, s, o);
        if (threadIdx.x == 0) sred[0] = 1.0f / fmaxf(sqrtf(s), 1e-12f);
    }
    __syncthreads();
    float inv = sred[0];
    for (int k = threadIdx.x; k < KCLS; k += 256)
        g_Bh[(size_t)k * DDIM + d] = __float2half(row[k] * inv);
}

// ---------------------------------------------------------------------------
// 3. HMMA GEMM + exp, single fp16 pass, 3-stage cp.async pipeline.
//    128x128 CTA tile; 8 warps (2m x 4n); K in 8 chunks of 32.
//    Last block computes r1 from (S, u0) and zeroes u.
// ---------------------------------------------------------------------------
#define CH 32
#define NCH 8
#define TILE_BYTES 8192                   // 128 rows x 64B
#define STAGE_BYTES (2 * TILE_BYTES)      // A, B
#define NSTAGE 3
#define SMEM_GEMM_TOTAL (NSTAGE * STAGE_BYTES + 512)
#define GEMM_GRID (8 * 96)

__device__ __forceinline__ void load_stage(uint32_t sbase, int buf, int b0, int n0,
                                           int c, int tid) {
    uint32_t dstb = sbase + (uint32_t)buf * STAGE_BYTES;
    #pragma unroll
    for (int j = 0; j < 2; j++) {
        int slot = tid + j * 256;          // 0..511
        int row  = slot >> 2;
        int c16  = slot & 3;
        uint32_t sw = SW64((uint32_t)(row * 64 + c16 * 16));
        size_t gA = (size_t)(b0 + row) * DDIM + c * CH + c16 * 8;
        size_t gB = (size_t)(n0 + row) * DDIM + c * CH + c16 * 8;
        cp_async16(dstb + 0 * TILE_BYTES + sw, &g_Ah[gA]);
        cp_async16(dstb + 1 * TILE_BYTES + sw, &g_Bh[gB]);
    }
}

__global__ __launch_bounds__(256, 2) void k_gemm_mma() {
    extern __shared__ char smem[];
    float* scol = reinterpret_cast<float*>(smem + NSTAGE * STAGE_BYTES);
    __shared__ int sLast;
    uint32_t sbase = smem_u32(smem);

    int tid = threadIdx.x, wid = tid >> 5, lane = tid & 31;
    int n0 = blockIdx.x * 128;
    int b0 = blockIdx.y * 128;
    int wm = (wid & 1) * 64;
    int wn = (wid >> 1) * 32;

    float acc[4][4][4];
    #pragma unroll
    for (int i = 0; i < 4; i++)
        #pragma unroll
        for (int j = 0; j < 4; j++)
            #pragma unroll
            for (int q = 0; q < 4; q++) acc[i][j][q] = 0.f;

    int a_row  = (lane & 7) + ((lane >> 3) & 1) * 8;
    int a_colb = (lane >> 4) * 16;
    int b_row  = (lane & 7) + ((lane >> 4) & 1) * 8;
    int b_colb = ((lane >> 3) & 1) * 16;

    #pragma unroll
    for (int s = 0; s < NSTAGE; s++) { load_stage(sbase, s, b0, n0, s, tid); cp_commit(); }

    for (int c = 0; c < NCH; c++) {
        cp_wait<NSTAGE - 1>();
        __syncthreads();
        uint32_t tb = sbase + (uint32_t)(c % NSTAGE) * STAGE_BYTES;

        #pragma unroll
        for (int ks = 0; ks < 2; ks++) {
            uint32_t a[4][4], bh[4][2];
            #pragma unroll
            for (int np = 0; np < 2; np++) {
                uint32_t sw = SW64((uint32_t)((wn + np * 16 + b_row) * 64 + ks * 32 + b_colb));
                ldsm_x4(bh[np*2][0], bh[np*2][1], bh[np*2+1][0], bh[np*2+1][1],
                        tb + 1 * TILE_BYTES + sw);
            }
            #pragma unroll
            for (int mt = 0; mt < 4; mt++) {
                uint32_t sw = SW64((uint32_t)((wm + mt * 16 + a_row) * 64 + ks * 32 + a_colb));
                ldsm_x4(a[mt][0], a[mt][1], a[mt][2], a[mt][3], tb + 0 * TILE_BYTES + sw);
            }
            #pragma unroll
            for (int mt = 0; mt < 4; mt++)
                #pragma unroll
                for (int nt = 0; nt < 4; nt++)
                    mma_f16(acc[mt][nt], a[mt], bh[nt]);
        }
        __syncthreads();
        if (c + NSTAGE < NCH) load_stage(sbase, c % NSTAGE, b0, n0, c + NSTAGE, tid);
        cp_commit();
    }

    // ---- Epilogue: exp, direct stores, column sums ----
    if (tid < 128) scol[tid] = 0.f;
    __syncthreads();

    int g = lane >> 2;
    int t2 = (lane & 3) * 2;
    float csum[4][2];
    #pragma unroll
    for (int nt = 0; nt < 4; nt++) { csum[nt][0] = 0.f; csum[nt][1] = 0.f; }

    #pragma unroll
    for (int mt = 0; mt < 4; mt++) {
        int r0 = b0 + wm + mt * 16 + g;
        #pragma unroll
        for (int nt = 0; nt < 4; nt++) {
            int col = n0 + wn + nt * 8 + t2;
            float2 e0, e1;
            e0.x = __expf(INV_EPS * acc[mt][nt][0]);
            e0.y = __expf(INV_EPS * acc[mt][nt][1]);
            e1.x = __expf(INV_EPS * acc[mt][nt][2]);
            e1.y = __expf(INV_EPS * acc[mt][nt][3]);
            *reinterpret_cast<float2*>(&g_E[(size_t)r0 * KPAD + col]) = e0;
            *reinterpret_cast<float2*>(&g_E[(size_t)(r0 + 8) * KPAD + col]) = e1;
            csum[nt][0] += e0.x + e1.x;
            csum[nt][1] += e0.y + e1.y;
        }
    }
    #pragma unroll
    for (int nt = 0; nt < 4; nt++) {
        atomicAdd(&scol[wn + nt * 8 + t2],     csum[nt][0]);
        atomicAdd(&scol[wn + nt * 8 + t2 + 1], csum[nt][1]);
    }
    __syncthreads();

    if (tid < 128) atomicAdd(&g_u[n0 + tid], scol[tid]);  // pads land in g_u[1000..1023]
    if (tid < 32) {
        float s = 0.f;
        #pragma unroll
        for (int i = 0; i < 4; i++) {
            int k = tid + i * 32;
            if (n0 + k < KCLS) s += scol[k];
        }
        s = warp_sum(s);
        if (tid == 0) atomicAdd(&g_S, (double)s);
    }

    // ---- Last block computes r1, zeroes u ----
    __threadfence();
    __syncthreads();
    if (tid == 0) sLast = (atomicAdd(&g_cnt, 1) == GEMM_GRID - 1);
    __syncthreads();
    if (sLast) finalize_r(tid);
}

// ---------------------------------------------------------------------------
// 4. Fused pass: warp-per-row, register uacc (R6 structure), PLUS
//    (a) fp32 cb (g_SfB precomputed; no DP divide in the loop)
//    (b) next-row double-buffer prefetch (loads overlap reduce+accumulate).
//    384 blocks x 8 warps x 4 rows = 12288. smem combine, one global flush.
// ---------------------------------------------------------------------------
#define VCU_GRID 384
#define VCU_ROWS 4
__global__ __launch_bounds__(256) void k_vcu() {
    __shared__ float ush[KPAD];
    __shared__ int sLast;
    int tid = threadIdx.x, warp = tid >> 5, lane = tid & 31;
    for (int k = tid; k < KPAD; k += 256) ush[k] = 0.f;
    __syncthreads();

    float SfB = g_SfB;
    const float4* r4 = reinterpret_cast<const float4*>(g_r);
    int base = (blockIdx.x * 8 + warp) * VCU_ROWS;

    float uacc[32];
    #pragma unroll
    for (int i = 0; i < 32; i++) uacc[i] = 0.f;

    float4 e[8], en[8];
    {
        const float4* E4 = reinterpret_cast<const float4*>(g_E + (size_t)base * KPAD);
        #pragma unroll
        for (int i = 0; i < 8; i++) e[i] = E4[lane + i * 32];
    }

    #pragma unroll
    for (int it = 0; it < VCU_ROWS; it++) {
        // Prefetch next row BEFORE the reduce (keeps the load stream busy)
        if (it + 1 < VCU_ROWS) {
            const float4* En4 =
                reinterpret_cast<const float4*>(g_E + (size_t)(base + it + 1) * KPAD);
            #pragma unroll
            for (int i = 0; i < 8; i++) en[i] = En4[lane + i * 32];
        }
        float v = 0.f;
        #pragma unroll
        for (int i = 0; i < 8; i++) {
            float4 r = __ldg(&r4[lane + i * 32]);
            v += e[i].x * r.x + e[i].y * r.y + e[i].z * r.z + e[i].w * r.w;
        }
        v = warp_sum(v);
        v = __shfl_sync(0xFFFFFFFFu, v, 0);
        float cb = SfB / v;                       // fp32 divide (no DP in loop)
        #pragma unroll
        for (int i = 0; i < 8; i++) {
            uacc[i * 4 + 0] += e[i].x * cb;
            uacc[i * 4 + 1] += e[i].y * cb;
            uacc[i * 4 + 2] += e[i].z * cb;
            uacc[i * 4 + 3] += e[i].w * cb;
        }
        if (it + 1 < VCU_ROWS) {
            #pragma unroll
            for (int i = 0; i < 8; i++) e[i] = en[i];
        }
    }

    // Per-warp flush into block smem (spread addresses, one pass)
    #pragma unroll
    for (int i = 0; i < 8; i++) {
        int k0 = 4 * (lane + i * 32);
        atomicAdd(&ush[k0 + 0], uacc[i * 4 + 0]);
        atomicAdd(&ush[k0 + 1], uacc[i * 4 + 1]);
        atomicAdd(&ush[k0 + 2], uacc[i * 4 + 2]);
        atomicAdd(&ush[k0 + 3], uacc[i * 4 + 3]);
    }
    __syncthreads();
    for (int k = tid; k < KPAD; k += 256) atomicAdd(&g_u[k], ush[k]);

    // ---- Last block computes next r, zeroes u ----
    __threadfence();
    __syncthreads();
    if (tid == 0) sLast = (atomicAdd(&g_cnt, 1) == VCU_GRID - 1);
    __syncthreads();
    if (sLast) finalize_r(tid);
}

// ---------------------------------------------------------------------------
// 5. Final fused pass (rows 0..4095): v_b = E[b,:].r3 ; out = E*r3/v_b.
//    512 blocks x 8 warps x 1 row (R6 structure).
// ---------------------------------------------------------------------------
__global__ __launch_bounds__(256) void k_final(float* __restrict__ out) {
    int warp = threadIdx.x >> 5, lane = threadIdx.x & 31;
    const float4* r4 = reinterpret_cast<const float4*>(g_r);

    int b = blockIdx.x * 8 + warp;
    const float4* E4 = reinterpret_cast<const float4*>(g_E + (size_t)b * KPAD);
    float4 e[8];
    #pragma unroll
    for (int i = 0; i < 8; i++) e[i] = E4[lane + i * 32];
    float v = 0.f;
    #pragma unroll
    for (int i = 0; i < 8; i++) {
        float4 r = __ldg(&r4[lane + i * 32]);
        v += e[i].x * r.x + e[i].y * r.y + e[i].z * r.z + e[i].w * r.w;
    }
    v = warp_sum(v);
    v = __shfl_sync(0xFFFFFFFFu, v, 0);
    float invv = 1.0f / v;
    float* orow = out + (size_t)b * KCLS;           // 4000*b bytes: 16B aligned
    #pragma unroll
    for (int i = 0; i < 8; i++) {
        int idx = lane + i * 32;                     // float4 index, valid < 250
        if (idx < KCLS / 4) {
            float4 r = __ldg(&r4[idx]);
            float4 o;
            o.x = e[i].x * r.x * invv;
            o.y = e[i].y * r.y * invv;
            o.z = e[i].z * r.z * invv;
            o.w = e[i].w * r.w * invv;
            *reinterpret_cast<float4*>(orow + idx * 4) = o;
        }
    }
}

// ---------------------------------------------------------------------------
extern "C" void kernel_launch(void* const* d_in, const int* in_sizes, int n_in,
                              void* d_out, int out_size) {
    const float* features = (const float*)d_in[0];
    const float* head     = (const float*)d_in[1];
    const float* queue    = (const float*)d_in[2];
    float* out = (float*)d_out;

    cudaFuncSetAttribute(k_gemm_mma, cudaFuncAttributeMaxDynamicSharedMemorySize,
                         SMEM_GEMM_TOTAL);

    k_prep_feat<<<(B_TOT * 32) / 256, 256>>>(features, queue);
    k_prep_head<<<DDIM, 256>>>(head);
    k_gemm_mma<<<dim3(KPAD / 128, B_TOT / 128), 256, SMEM_GEMM_TOTAL>>>();  // + r1
    k_vcu<<<VCU_GRID, 256>>>();   // iter1 col-step + iter2 row-sum -> r2
    k_vcu<<<VCU_GRID, 256>>>();   // iter2 col-step + iter3 row-sum -> r3
    k_final<<<512, 256>>>(out);   // iter3 col-step fused with output
}